// round 2
// baseline (speedup 1.0000x reference)
#include <cuda_runtime.h>
#include <math.h>

static constexpr int BB = 8;
static constexpr int CC = 96;
static constexpr int C2 = 192;
static constexpr int C4 = 384;
static constexpr int NN = 3136;   // 56*56
static constexpr int KK = 9;
static constexpr float EPS_ = 1e-5f;

// ---------------- scratch (no allocations allowed) ----------------
__device__ float g_act[BB * CC * NN];
__device__ float g_t1 [BB * CC * NN];
__device__ float g_xf [BB * CC * NN];
__device__ float g_xn [BB * CC * NN];
__device__ float g_sq [BB * NN];
__device__ int   g_idx[BB * NN * KK];
__device__ float g_big[BB * C4 * NN];   // ffn hidden; also 2C y2 + 2C t3 for grapher

// ---------------- 1x1 conv == batched GEMM: out[b,o,n] = sum_c W[o,c] X[b,c,n] + bias[o]
__global__ __launch_bounds__(256) void gemm_bias_kernel(
    const float* __restrict__ X, const float* __restrict__ W,
    const float* __restrict__ bias, float* __restrict__ out,
    int Cout, int Cin)
{
    int b  = blockIdx.z;
    int n0 = blockIdx.x * 64;
    int o0 = blockIdx.y * 64;
    int tid = threadIdx.x;
    int ty = tid >> 4, tx = tid & 15;
    __shared__ float Ws[32][65];   // [k][o], padded
    __shared__ float Xs[32][64];   // [k][n]
    float acc[4][4] = {};
    const float* Xb = X + (size_t)b * Cin * NN;
    for (int kt = 0; kt < Cin; kt += 32) {
        for (int t = tid; t < 64 * 32; t += 256) {
            int o = t >> 5, k = t & 31;
            float w = 0.f;
            if (o0 + o < Cout) w = W[(size_t)(o0 + o) * Cin + kt + k];
            Ws[k][o] = w;
        }
        for (int t = tid; t < 32 * 64; t += 256) {
            int k = t >> 6, nn = t & 63;
            Xs[k][nn] = Xb[(size_t)(kt + k) * NN + n0 + nn];
        }
        __syncthreads();
        #pragma unroll 8
        for (int k = 0; k < 32; k++) {
            float a[4], bv[4];
            #pragma unroll
            for (int i = 0; i < 4; i++) a[i] = Ws[k][ty * 4 + i];
            #pragma unroll
            for (int j = 0; j < 4; j++) bv[j] = Xs[k][tx + 16 * j];
            #pragma unroll
            for (int i = 0; i < 4; i++)
                #pragma unroll
                for (int j = 0; j < 4; j++)
                    acc[i][j] = fmaf(a[i], bv[j], acc[i][j]);
        }
        __syncthreads();
    }
    #pragma unroll
    for (int i = 0; i < 4; i++) {
        int o = o0 + ty * 4 + i;
        if (o < Cout) {
            float bvv = bias[o];
            float* op = out + ((size_t)b * Cout + o) * NN + n0;
            #pragma unroll
            for (int j = 0; j < 4; j++) op[tx + 16 * j] = acc[i][j] + bvv;
        }
    }
}

// ---------------- instance norm per (b,c) row over N; optional act + residual
// act: 0 none, 1 exact gelu, 2 relu
__global__ __launch_bounds__(256) void inorm_kernel(
    const float* __restrict__ in, float* __restrict__ out,
    const float* __restrict__ res, int act)
{
    int row = blockIdx.x;
    const float* p = in + (size_t)row * NN;
    int tid = threadIdx.x;
    float s = 0.f, s2 = 0.f;
    for (int i = tid; i < NN; i += 256) { float v = p[i]; s += v; s2 += v * v; }
    __shared__ float r0s[256], r1s[256];
    r0s[tid] = s; r1s[tid] = s2;
    __syncthreads();
    for (int st = 128; st > 0; st >>= 1) {
        if (tid < st) { r0s[tid] += r0s[tid + st]; r1s[tid] += r1s[tid + st]; }
        __syncthreads();
    }
    __shared__ float msh, rsh;
    if (tid == 0) {
        float mean = r0s[0] * (1.f / NN);
        float var  = r1s[0] * (1.f / NN) - mean * mean;
        msh = mean; rsh = rsqrtf(var + EPS_);
    }
    __syncthreads();
    float mean = msh, rstd = rsh;
    const float* rq = res ? res + (size_t)row * NN : nullptr;
    float* op = out + (size_t)row * NN;
    for (int i = tid; i < NN; i += 256) {
        float v = (p[i] - mean) * rstd;
        if (act == 1) v = 0.5f * v * (1.f + erff(v * 0.70710678118654752f));
        else if (act == 2) v = fmaxf(v, 0.f);
        if (rq) v += rq[i];
        op[i] = v;
    }
}

// ---------------- l2 normalize over channel dim per (b,n); also emit sq = ||xn||^2
__global__ __launch_bounds__(256) void l2norm_kernel(
    const float* __restrict__ xf, float* __restrict__ xn, float* __restrict__ sq)
{
    int t = blockIdx.x * 256 + threadIdx.x;
    if (t >= BB * NN) return;
    int b = t / NN, n = t - b * NN;
    const float* p = xf + (size_t)b * CC * NN + n;
    float s = 0.f;
    #pragma unroll 16
    for (int c = 0; c < CC; c++) { float v = p[(size_t)c * NN]; s += v * v; }
    float inv = 1.f / fmaxf(sqrtf(s), 1e-12f);
    float* q = xn + (size_t)b * CC * NN + n;
    #pragma unroll 16
    for (int c = 0; c < CC; c++) q[(size_t)c * NN] = p[(size_t)c * NN] * inv;
    sq[t] = s * inv * inv;
}

// ---------------- fused pairwise distance + top-9 smallest
// block = 128 threads, 32 rows (n), m-tiles of 64; thread owns 2 rows x (m%8 subset)
__device__ __forceinline__ void tk_insert(float v, int m, float* tv, int* ti,
                                          float& wv, int& wi)
{
    if (v < wv) {
        tv[wi] = v; ti[wi] = m;
        wv = tv[0]; wi = 0;
        #pragma unroll
        for (int k = 1; k < KK; k++) if (tv[k] > wv) { wv = tv[k]; wi = k; }
    }
}

__global__ __launch_bounds__(128) void dist_topk_kernel(
    const float* __restrict__ xn, const float* __restrict__ sq,
    const float* __restrict__ rp, int* __restrict__ oidx)
{
    int b = blockIdx.y;
    int n0 = blockIdx.x * 32;
    int tid = threadIdx.x;
    int mr = tid >> 3;      // 0..15
    int mc = tid & 7;       // 0..7
    int r0 = mr * 2, r1 = r0 + 1;

    __shared__ float Xn_s[CC * 32];   // 12 KB
    __shared__ float sh2[CC * 64];    // 24 KB: Xm tile during loop, topk merge after

    const float* xb = xn + (size_t)b * CC * NN;
    for (int t = tid; t < CC * 32; t += 128) {
        int c = t >> 5, r = t & 31;
        Xn_s[c * 32 + r] = xb[(size_t)c * NN + n0 + r];
    }
    __syncthreads();

    float sqn0 = sq[b * NN + n0 + r0];
    float sqn1 = sq[b * NN + n0 + r1];

    float tv0[KK], tv1[KK]; int ti0[KK], ti1[KK];
    #pragma unroll
    for (int k = 0; k < KK; k++) { tv0[k] = 1e30f; tv1[k] = 1e30f; ti0[k] = 0; ti1[k] = 0; }
    float wv0 = 1e30f, wv1 = 1e30f; int wi0 = 0, wi1 = 0;

    for (int m0 = 0; m0 < NN; m0 += 64) {
        __syncthreads();
        for (int t = tid; t < CC * 64; t += 128) {
            int c = t >> 6, mm = t & 63;
            sh2[c * 64 + mm] = xb[(size_t)c * NN + m0 + mm];
        }
        __syncthreads();
        float acc0[8] = {}, acc1[8] = {};
        #pragma unroll 4
        for (int c = 0; c < CC; c++) {
            float a0 = Xn_s[c * 32 + r0];
            float a1 = Xn_s[c * 32 + r1];
            #pragma unroll
            for (int j = 0; j < 8; j++) {
                float bv = sh2[c * 64 + mc + 8 * j];
                acc0[j] = fmaf(a0, bv, acc0[j]);
                acc1[j] = fmaf(a1, bv, acc1[j]);
            }
        }
        const float* rpr0 = rp + (size_t)(n0 + r0) * NN + m0;
        const float* rpr1 = rp + (size_t)(n0 + r1) * NN + m0;
        const float* sqm  = sq + b * NN + m0;
        #pragma unroll
        for (int j = 0; j < 8; j++) {
            int mm = mc + 8 * j;
            int m = m0 + mm;
            float sm = sqm[mm];
            float d0 = sqn0 + sm - 2.f * acc0[j] + rpr0[mm];
            float d1 = sqn1 + sm - 2.f * acc1[j] + rpr1[mm];
            tk_insert(d0, m, tv0, ti0, wv0, wi0);
            tk_insert(d1, m, tv1, ti1, wv1, wi1);
        }
    }

    __syncthreads();   // done with Xm tile; reuse sh2 for merge
    float* cv = sh2;                        // [32][8][9] values
    int*   ci = (int*)(sh2 + 32 * 8 * KK);  // [32][8][9] indices
    #pragma unroll
    for (int k = 0; k < KK; k++) {
        cv[(r0 * 8 + mc) * KK + k] = tv0[k]; ci[(r0 * 8 + mc) * KK + k] = ti0[k];
        cv[(r1 * 8 + mc) * KK + k] = tv1[k]; ci[(r1 * 8 + mc) * KK + k] = ti1[k];
    }
    __syncthreads();
    if (tid < 32) {
        float* rv = cv + tid * 8 * KK;
        int*   ri = ci + tid * 8 * KK;
        int* op = oidx + ((size_t)b * NN + n0 + tid) * KK;
        for (int k = 0; k < KK; k++) {
            float best = 2e30f; int bi = 0, bt = 0;
            for (int t = 0; t < 8 * KK; t++) {
                float v = rv[t];
                if (v < best) { best = v; bi = ri[t]; bt = t; }
            }
            rv[bt] = 3e30f;   // consume
            op[k] = bi;
        }
    }
}

// ---------------- gather neighbors, max(x_j - x_i), write channel-interleaved (B,2C,N)
__global__ __launch_bounds__(256) void aggregate_kernel(
    const float* __restrict__ xf, const int* __restrict__ idx, float* __restrict__ y)
{
    int bc = blockIdx.x;            // b*CC + c
    __shared__ float row[NN];
    const float* p = xf + (size_t)bc * NN;
    for (int i = threadIdx.x; i < NN; i += 256) row[i] = p[i];
    __syncthreads();
    int b = bc / CC, c = bc - b * CC;
    const int* ip = idx + (size_t)b * NN * KK;
    float* y0 = y + ((size_t)b * C2 + 2 * c) * NN;
    float* y1 = y0 + NN;
    for (int n = threadIdx.x; n < NN; n += 256) {
        float xi = row[n];
        float mx = -3e38f;
        #pragma unroll
        for (int k = 0; k < KK; k++) {
            int j = ip[n * KK + k];
            mx = fmaxf(mx, row[j] - xi);
        }
        y0[n] = xi;
        y1[n] = mx;
    }
}

// ---------------- host orchestration ----------------
static void run_conv(const float* X, const float* W, const float* bias,
                     float* out, int Cout, int Cin)
{
    dim3 g(NN / 64, (Cout + 63) / 64, BB);
    gemm_bias_kernel<<<g, 256>>>(X, W, bias, out, Cout, Cin);
}
static void run_inorm(const float* in, float* out, const float* res, int Crows, int act)
{
    inorm_kernel<<<BB * Crows, 256>>>(in, out, res, act);
}

extern "C" void kernel_launch(void* const* d_in, const int* in_sizes, int n_in,
                              void* d_out, int out_size)
{
    (void)in_sizes; (void)n_in; (void)out_size;
    const float* x  = (const float*)d_in[0];
    const float* rp = (const float*)d_in[1];
    const float* P[20];
    for (int i = 0; i < 20; i++) P[i] = (const float*)d_in[2 + i];
    // P[0..5]=g1(fc1_w,fc1_b,mr_w,mr_b,fc2_w,fc2_b) P[6..11]=g2
    // P[12..15]=f1(fc1_w,fc1_b,fc2_w,fc2_b)         P[16..19]=f2

    float *act, *t1, *xf, *xnp, *sqp, *big; int* idxp;
    cudaGetSymbolAddress((void**)&act,  g_act);
    cudaGetSymbolAddress((void**)&t1,   g_t1);
    cudaGetSymbolAddress((void**)&xf,   g_xf);
    cudaGetSymbolAddress((void**)&xnp,  g_xn);
    cudaGetSymbolAddress((void**)&sqp,  g_sq);
    cudaGetSymbolAddress((void**)&idxp, g_idx);
    cudaGetSymbolAddress((void**)&big,  g_big);
    float* y2 = big;                          // (B,2C,N)
    float* t3 = big + (size_t)BB * C2 * NN;   // (B,2C,N)
    float* out = (float*)d_out;

    auto grapher = [&](const float* inx,
                       const float* w1, const float* b1,
                       const float* mw, const float* mb,
                       const float* w2, const float* b2, float* outp) {
        run_conv(inx, w1, b1, t1, CC, CC);
        run_inorm(t1, xf, nullptr, CC, 0);                          // xf
        l2norm_kernel<<<(BB * NN + 255) / 256, 256>>>(xf, xnp, sqp);
        dim3 dg(NN / 32, BB);
        dist_topk_kernel<<<dg, 128>>>(xnp, sqp, rp, idxp);
        aggregate_kernel<<<BB * CC, 256>>>(xf, idxp, y2);           // (B,2C,N)
        run_conv(y2, mw, mb, t3, C2, C2);
        run_inorm(t3, t3, nullptr, C2, 1);                          // gelu, in-place
        run_conv(t3, w2, b2, t1, CC, C2);
        run_inorm(t1, outp, inx, CC, 0);                            // + shortcut
    };
    auto ffn = [&](float* a, const float* w1, const float* b1,
                   const float* w2, const float* b2) {
        run_conv(a, w1, b1, big, C4, CC);
        run_inorm(big, big, nullptr, C4, 1);                        // gelu, in-place
        run_conv(big, w2, b2, t1, CC, C4);
        run_inorm(t1, a, a, CC, 0);                                 // + shortcut
    };

    grapher(x, P[0], P[1], P[2], P[3], P[4], P[5], act);
    ffn(act, P[12], P[13], P[14], P[15]);
    run_inorm(act, act, nullptr, CC, 2);                            // relu(inorm)
    grapher(act, P[6], P[7], P[8], P[9], P[10], P[11], act);
    ffn(act, P[16], P[17], P[18], P[19]);
    run_inorm(act, out, x, CC, 0);                                  // x + inorm(y)
}

// round 5
// speedup vs baseline: 1.1652x; 1.1652x over previous
#include <cuda_runtime.h>
#include <math.h>

static constexpr int BB = 8;
static constexpr int CC = 96;
static constexpr int C2 = 192;
static constexpr int C4 = 384;
static constexpr int NN = 3136;   // 56*56
static constexpr int KK = 9;
static constexpr float EPS_ = 1e-5f;

// ---------------- scratch (no allocations allowed) ----------------
__device__ float g_act[BB * CC * NN];
__device__ float g_t1 [BB * CC * NN];
__device__ float g_xf [BB * CC * NN];
__device__ float g_xn [BB * CC * NN];
__device__ float g_sq [BB * NN];
__device__ int   g_idx[BB * NN * KK];
__device__ float g_big[BB * C4 * NN];   // ffn hidden; also 2C y2 + 2C t3 for grapher

// ---------------- 1x1 conv == batched GEMM: out[b,o,n] = sum_c W[o,c] X[b,c,n] + bias[o]
// 128 threads, 64x64 tile, thread = 4 o-rows x 8 n-cols (two float4 groups)
__global__ __launch_bounds__(128) void gemm_bias_kernel(
    const float* __restrict__ X, const float* __restrict__ W,
    const float* __restrict__ bias, float* __restrict__ out,
    int Cout, int Cin)
{
    int b  = blockIdx.z;
    int n0 = blockIdx.x * 64;
    int o0 = blockIdx.y * 64;
    int tid = threadIdx.x;
    int ty4 = (tid >> 3) * 4;   // 0..60 step 4
    int tx4 = (tid & 7) * 4;    // 0..28 step 4
    __shared__ float Ws[32][64];   // [k][o]
    __shared__ float Xs[32][64];   // [k][n]
    float acc[4][8] = {};
    const float* Xb = X + (size_t)b * Cin * NN;

    for (int kt = 0; kt < Cin; kt += 32) {
        // load W tile (transpose k-quads -> [k][o])
        for (int t = tid; t < 512; t += 128) {
            int o = t & 63, kq = t >> 6;
            float4 w = make_float4(0.f, 0.f, 0.f, 0.f);
            if (o0 + o < Cout)
                w = *(const float4*)&W[(size_t)(o0 + o) * Cin + kt + kq * 4];
            Ws[kq * 4 + 0][o] = w.x;
            Ws[kq * 4 + 1][o] = w.y;
            Ws[kq * 4 + 2][o] = w.z;
            Ws[kq * 4 + 3][o] = w.w;
        }
        // load X tile
        for (int t = tid; t < 512; t += 128) {
            int k = t >> 4, nq = t & 15;
            *(float4*)&Xs[k][nq * 4] =
                *(const float4*)&Xb[(size_t)(kt + k) * NN + n0 + nq * 4];
        }
        __syncthreads();
        #pragma unroll 8
        for (int k = 0; k < 32; k++) {
            float4 a  = *(const float4*)&Ws[k][ty4];
            float4 bl = *(const float4*)&Xs[k][tx4];
            float4 br = *(const float4*)&Xs[k][32 + tx4];
            float av[4] = {a.x, a.y, a.z, a.w};
            float bv[8] = {bl.x, bl.y, bl.z, bl.w, br.x, br.y, br.z, br.w};
            #pragma unroll
            for (int i = 0; i < 4; i++)
                #pragma unroll
                for (int j = 0; j < 8; j++)
                    acc[i][j] = fmaf(av[i], bv[j], acc[i][j]);
        }
        __syncthreads();
    }
    #pragma unroll
    for (int i = 0; i < 4; i++) {
        int o = o0 + ty4 + i;
        if (o < Cout) {
            float bvv = bias[o];
            float* op = out + ((size_t)b * Cout + o) * NN + n0;
            float4 vL = make_float4(acc[i][0] + bvv, acc[i][1] + bvv,
                                    acc[i][2] + bvv, acc[i][3] + bvv);
            float4 vR = make_float4(acc[i][4] + bvv, acc[i][5] + bvv,
                                    acc[i][6] + bvv, acc[i][7] + bvv);
            *(float4*)&op[tx4]      = vL;
            *(float4*)&op[32 + tx4] = vR;
        }
    }
}

// ---------------- instance norm per (b,c) row over N; optional act + residual
// act: 0 none, 1 exact gelu, 2 relu
__global__ __launch_bounds__(256) void inorm_kernel(
    const float* __restrict__ in, float* __restrict__ out,
    const float* __restrict__ res, int act)
{
    int row = blockIdx.x;
    const float* p = in + (size_t)row * NN;
    int tid = threadIdx.x;
    float s = 0.f, s2 = 0.f;
    for (int i = tid; i < NN; i += 256) { float v = p[i]; s += v; s2 += v * v; }
    __shared__ float r0s[256], r1s[256];
    r0s[tid] = s; r1s[tid] = s2;
    __syncthreads();
    for (int st = 128; st > 0; st >>= 1) {
        if (tid < st) { r0s[tid] += r0s[tid + st]; r1s[tid] += r1s[tid + st]; }
        __syncthreads();
    }
    __shared__ float msh, rsh;
    if (tid == 0) {
        float mean = r0s[0] * (1.f / NN);
        float var  = r1s[0] * (1.f / NN) - mean * mean;
        msh = mean; rsh = rsqrtf(var + EPS_);
    }
    __syncthreads();
    float mean = msh, rstd = rsh;
    const float* rq = res ? res + (size_t)row * NN : nullptr;
    float* op = out + (size_t)row * NN;
    for (int i = tid; i < NN; i += 256) {
        float v = (p[i] - mean) * rstd;
        if (act == 1) v = 0.5f * v * (1.f + erff(v * 0.70710678118654752f));
        else if (act == 2) v = fmaxf(v, 0.f);
        if (rq) v += rq[i];
        op[i] = v;
    }
}

// ---------------- l2 normalize over channel dim per (b,n); also emit sq = ||xn||^2
__global__ __launch_bounds__(256) void l2norm_kernel(
    const float* __restrict__ xf, float* __restrict__ xn, float* __restrict__ sq)
{
    int t = blockIdx.x * 256 + threadIdx.x;
    if (t >= BB * NN) return;
    int b = t / NN, n = t - b * NN;
    const float* p = xf + (size_t)b * CC * NN + n;
    float s = 0.f;
    #pragma unroll 16
    for (int c = 0; c < CC; c++) { float v = p[(size_t)c * NN]; s += v * v; }
    float inv = 1.f / fmaxf(sqrtf(s), 1e-12f);
    float* q = xn + (size_t)b * CC * NN + n;
    #pragma unroll 16
    for (int c = 0; c < CC; c++) q[(size_t)c * NN] = p[(size_t)c * NN] * inv;
    sq[t] = s * inv * inv;
}

// ---------------- fused pairwise distance + top-9 smallest
// block 128 threads, 32 n-rows, m-tiles of 64
// thread = 2 n-rows x 8 m-cols; m-cols are two contiguous float4 groups:
//   {mc*4+i} and {32+mc*4+i}  -> vectorized LDS.128, conflict-free
__device__ __forceinline__ void tk_insert(float v, int m, float* tv, int* ti,
                                          float& wv, int& wi)
{
    if (v < wv) {
        tv[wi] = v; ti[wi] = m;
        wv = tv[0]; wi = 0;
        #pragma unroll
        for (int k = 1; k < KK; k++) if (tv[k] > wv) { wv = tv[k]; wi = k; }
    }
}

__global__ __launch_bounds__(128) void dist_topk_kernel(
    const float* __restrict__ xn, const float* __restrict__ sq,
    const float* __restrict__ rp, int* __restrict__ oidx)
{
    int b = blockIdx.y;
    int n0 = blockIdx.x * 32;
    int tid = threadIdx.x;
    int mr  = tid >> 3;      // 0..15
    int mc4 = (tid & 7) * 4; // 0..28
    int r0 = mr * 2, r1 = r0 + 1;

    __shared__ float Xn_s[CC * 32];   // 12 KB, [c][32]
    __shared__ float sh2[CC * 64];    // 24 KB, [c][64]; reused for merge

    const float* xb = xn + (size_t)b * CC * NN;
    for (int t = tid; t < CC * 8; t += 128) {        // 768 float4s
        int c = t >> 3, q = (t & 7) * 4;
        *(float4*)&Xn_s[c * 32 + q] = *(const float4*)&xb[(size_t)c * NN + n0 + q];
    }
    __syncthreads();

    float sqn0 = sq[b * NN + n0 + r0];
    float sqn1 = sq[b * NN + n0 + r1];

    float tv0[KK], tv1[KK]; int ti0[KK], ti1[KK];
    #pragma unroll
    for (int k = 0; k < KK; k++) { tv0[k] = 1e30f; tv1[k] = 1e30f; ti0[k] = 0; ti1[k] = 0; }
    float wv0 = 1e30f, wv1 = 1e30f; int wi0 = 0, wi1 = 0;

    for (int m0 = 0; m0 < NN; m0 += 64) {
        __syncthreads();
        for (int t = tid; t < CC * 16; t += 128) {   // 1536 float4s
            int c = t >> 4, q = (t & 15) * 4;
            *(float4*)&sh2[c * 64 + q] = *(const float4*)&xb[(size_t)c * NN + m0 + q];
        }
        __syncthreads();
        float acc0[8] = {}, acc1[8] = {};
        #pragma unroll 8
        for (int c = 0; c < CC; c++) {
            float2 a  = *(const float2*)&Xn_s[c * 32 + r0];
            float4 bl = *(const float4*)&sh2[c * 64 + mc4];
            float4 br = *(const float4*)&sh2[c * 64 + 32 + mc4];
            float bv[8] = {bl.x, bl.y, bl.z, bl.w, br.x, br.y, br.z, br.w};
            #pragma unroll
            for (int j = 0; j < 8; j++) {
                acc0[j] = fmaf(a.x, bv[j], acc0[j]);
                acc1[j] = fmaf(a.y, bv[j], acc1[j]);
            }
        }
        // epilogue: dist + topk insert (all 16B-aligned vector loads)
        const float* sqm = sq + b * NN + m0;
        float4 sqL = *(const float4*)&sqm[mc4];
        float4 sqR = *(const float4*)&sqm[32 + mc4];
        const float* rpr0 = rp + (size_t)(n0 + r0) * NN + m0;
        const float* rpr1 = rp + (size_t)(n0 + r1) * NN + m0;
        float4 rp0L = *(const float4*)&rpr0[mc4];
        float4 rp0R = *(const float4*)&rpr0[32 + mc4];
        float4 rp1L = *(const float4*)&rpr1[mc4];
        float4 rp1R = *(const float4*)&rpr1[32 + mc4];
        float sqv[8] = {sqL.x, sqL.y, sqL.z, sqL.w, sqR.x, sqR.y, sqR.z, sqR.w};
        float r0v[8] = {rp0L.x, rp0L.y, rp0L.z, rp0L.w, rp0R.x, rp0R.y, rp0R.z, rp0R.w};
        float r1v[8] = {rp1L.x, rp1L.y, rp1L.z, rp1L.w, rp1R.x, rp1R.y, rp1R.z, rp1R.w};
        #pragma unroll
        for (int j = 0; j < 8; j++) {
            int m = m0 + (j < 4 ? mc4 + j : 32 + mc4 + (j - 4));
            float d0 = fmaf(-2.f, acc0[j], sqn0 + sqv[j] + r0v[j]);
            float d1 = fmaf(-2.f, acc1[j], sqn1 + sqv[j] + r1v[j]);
            tk_insert(d0, m, tv0, ti0, wv0, wi0);
            tk_insert(d1, m, tv1, ti1, wv1, wi1);
        }
    }

    __syncthreads();   // done with Xm tile; reuse sh2 for merge
    float* cv = sh2;                        // [32][8][9] values
    int*   ci = (int*)(sh2 + 32 * 8 * KK);  // [32][8][9] indices
    int mc = tid & 7;
    #pragma unroll
    for (int k = 0; k < KK; k++) {
        cv[(r0 * 8 + mc) * KK + k] = tv0[k]; ci[(r0 * 8 + mc) * KK + k] = ti0[k];
        cv[(r1 * 8 + mc) * KK + k] = tv1[k]; ci[(r1 * 8 + mc) * KK + k] = ti1[k];
    }
    __syncthreads();
    if (tid < 32) {
        float* rv = cv + tid * 8 * KK;
        int*   ri = ci + tid * 8 * KK;
        int* op = oidx + ((size_t)b * NN + n0 + tid) * KK;
        for (int k = 0; k < KK; k++) {
            float best = 2e30f; int bi = 0, bt = 0;
            for (int t = 0; t < 8 * KK; t++) {
                float v = rv[t];
                if (v < best) { best = v; bi = ri[t]; bt = t; }
            }
            rv[bt] = 3e30f;   // consume
            op[k] = bi;
        }
    }
}

// ---------------- gather neighbors, max(x_j - x_i), write channel-interleaved (B,2C,N)
__global__ __launch_bounds__(256) void aggregate_kernel(
    const float* __restrict__ xf, const int* __restrict__ idx, float* __restrict__ y)
{
    int bc = blockIdx.x;            // b*CC + c
    __shared__ float row[NN];
    const float* p = xf + (size_t)bc * NN;
    for (int i = threadIdx.x; i < NN; i += 256) row[i] = p[i];
    __syncthreads();
    int b = bc / CC, c = bc - b * CC;
    const int* ip = idx + (size_t)b * NN * KK;
    float* y0 = y + ((size_t)b * C2 + 2 * c) * NN;
    float* y1 = y0 + NN;
    for (int n = threadIdx.x; n < NN; n += 256) {
        float xi = row[n];
        float mx = -3e38f;
        #pragma unroll
        for (int k = 0; k < KK; k++) {
            int j = ip[n * KK + k];
            mx = fmaxf(mx, row[j] - xi);
        }
        y0[n] = xi;
        y1[n] = mx;
    }
}

// ---------------- host orchestration ----------------
static void run_conv(const float* X, const float* W, const float* bias,
                     float* out, int Cout, int Cin)
{
    dim3 g(NN / 64, (Cout + 63) / 64, BB);
    gemm_bias_kernel<<<g, 128>>>(X, W, bias, out, Cout, Cin);
}
static void run_inorm(const float* in, float* out, const float* res, int Crows, int act)
{
    inorm_kernel<<<BB * Crows, 256>>>(in, out, res, act);
}

extern "C" void kernel_launch(void* const* d_in, const int* in_sizes, int n_in,
                              void* d_out, int out_size)
{
    (void)in_sizes; (void)n_in; (void)out_size;
    const float* x  = (const float*)d_in[0];
    const float* rp = (const float*)d_in[1];
    const float* P[20];
    for (int i = 0; i < 20; i++) P[i] = (const float*)d_in[2 + i];

    float *act, *t1, *xf, *xnp, *sqp, *big; int* idxp;
    cudaGetSymbolAddress((void**)&act,  g_act);
    cudaGetSymbolAddress((void**)&t1,   g_t1);
    cudaGetSymbolAddress((void**)&xf,   g_xf);
    cudaGetSymbolAddress((void**)&xnp,  g_xn);
    cudaGetSymbolAddress((void**)&sqp,  g_sq);
    cudaGetSymbolAddress((void**)&idxp, g_idx);
    cudaGetSymbolAddress((void**)&big,  g_big);
    float* y2 = big;                          // (B,2C,N)
    float* t3 = big + (size_t)BB * C2 * NN;   // (B,2C,N)
    float* out = (float*)d_out;

    auto grapher = [&](const float* inx,
                       const float* w1, const float* b1,
                       const float* mw, const float* mb,
                       const float* w2, const float* b2, float* outp) {
        run_conv(inx, w1, b1, t1, CC, CC);
        run_inorm(t1, xf, nullptr, CC, 0);                          // xf
        l2norm_kernel<<<(BB * NN + 255) / 256, 256>>>(xf, xnp, sqp);
        dim3 dg(NN / 32, BB);
        dist_topk_kernel<<<dg, 128>>>(xnp, sqp, rp, idxp);
        aggregate_kernel<<<BB * CC, 256>>>(xf, idxp, y2);           // (B,2C,N)
        run_conv(y2, mw, mb, t3, C2, C2);
        run_inorm(t3, t3, nullptr, C2, 1);                          // gelu, in-place
        run_conv(t3, w2, b2, t1, CC, C2);
        run_inorm(t1, outp, inx, CC, 0);                            // + shortcut
    };
    auto ffn = [&](float* a, const float* w1, const float* b1,
                   const float* w2, const float* b2) {
        run_conv(a, w1, b1, big, C4, CC);
        run_inorm(big, big, nullptr, C4, 1);                        // gelu, in-place
        run_conv(big, w2, b2, t1, CC, C4);
        run_inorm(t1, a, a, CC, 0);                                 // + shortcut
    };

    grapher(x, P[0], P[1], P[2], P[3], P[4], P[5], act);
    ffn(act, P[12], P[13], P[14], P[15]);
    run_inorm(act, act, nullptr, CC, 2);                            // relu(inorm)
    grapher(act, P[6], P[7], P[8], P[9], P[10], P[11], act);
    ffn(act, P[16], P[17], P[18], P[19]);
    run_inorm(act, out, x, CC, 0);                                  // x + inorm(y)
}

// round 6
// speedup vs baseline: 1.1918x; 1.0228x over previous
#include <cuda_runtime.h>
#include <math.h>

static constexpr int BB = 8;
static constexpr int CC = 96;
static constexpr int C2 = 192;
static constexpr int C4 = 384;
static constexpr int NN = 3136;   // 56*56
static constexpr int KK = 9;
static constexpr float EPS_ = 1e-5f;

// ---------------- scratch (no allocations allowed) ----------------
__device__ float g_act[BB * CC * NN];
__device__ float g_t1 [BB * CC * NN];
__device__ float g_xf [BB * CC * NN];
__device__ float g_xn [BB * CC * NN];
__device__ float g_sq [BB * NN];
__device__ int   g_idx[BB * NN * KK];
__device__ float g_big[BB * C4 * NN];   // ffn hidden; also 2C y2 + 2C t3 for grapher

// ---------------- packed f32x2 helpers (FFMA2 via PTX) ----------------
typedef unsigned long long ull;
__device__ __forceinline__ ull pack2(float lo, float hi) {
    ull r;
    asm("mov.b64 %0, {%1, %2};" : "=l"(r) : "f"(lo), "f"(hi));
    return r;
}
__device__ __forceinline__ void ffma2(ull& d, ull a, ull b) {
    asm("fma.rn.f32x2 %0, %1, %2, %3;" : "=l"(d) : "l"(a), "l"(b), "l"(d));
}
__device__ __forceinline__ float2 unpack2(ull v) {
    float2 f;
    asm("mov.b64 {%0, %1}, %2;" : "=f"(f.x), "=f"(f.y) : "l"(v));
    return f;
}

// ---------------- 1x1 conv == batched GEMM: out[b,o,n] = sum_c W[o,c] X[b,c,n] + bias[o]
// 128 threads, 64x64 tile, thread = 4 o-rows x 8 n-cols (4 f32x2 pairs)
__global__ __launch_bounds__(128) void gemm_bias_kernel(
    const float* __restrict__ X, const float* __restrict__ W,
    const float* __restrict__ bias, float* __restrict__ out,
    int Cout, int Cin)
{
    int b  = blockIdx.z;
    int n0 = blockIdx.x * 64;
    int o0 = blockIdx.y * 64;
    int tid = threadIdx.x;
    int ty4 = (tid >> 3) * 4;   // 0..60 step 4
    int tx4 = (tid & 7) * 4;    // 0..28 step 4
    __shared__ float Ws[32][64];   // [k][o]
    __shared__ float Xs[32][64];   // [k][n]
    ull acc[4][4];
    #pragma unroll
    for (int i = 0; i < 4; i++)
        #pragma unroll
        for (int j = 0; j < 4; j++) acc[i][j] = 0ull;
    const float* Xb = X + (size_t)b * Cin * NN;

    for (int kt = 0; kt < Cin; kt += 32) {
        for (int t = tid; t < 512; t += 128) {
            int o = t & 63, kq = t >> 6;
            float4 w = make_float4(0.f, 0.f, 0.f, 0.f);
            if (o0 + o < Cout)
                w = *(const float4*)&W[(size_t)(o0 + o) * Cin + kt + kq * 4];
            Ws[kq * 4 + 0][o] = w.x;
            Ws[kq * 4 + 1][o] = w.y;
            Ws[kq * 4 + 2][o] = w.z;
            Ws[kq * 4 + 3][o] = w.w;
        }
        for (int t = tid; t < 512; t += 128) {
            int k = t >> 4, nq = t & 15;
            *(float4*)&Xs[k][nq * 4] =
                *(const float4*)&Xb[(size_t)(kt + k) * NN + n0 + nq * 4];
        }
        __syncthreads();
        #pragma unroll 8
        for (int k = 0; k < 32; k++) {
            float4 a = *(const float4*)&Ws[k][ty4];           // quarter-warp broadcast
            ulonglong2 bl = *(const ulonglong2*)&Xs[k][tx4];  // free f32x2 pairs
            ulonglong2 br = *(const ulonglong2*)&Xs[k][32 + tx4];
            ull bp[4] = {bl.x, bl.y, br.x, br.y};
            ull ap[4] = {pack2(a.x, a.x), pack2(a.y, a.y),
                         pack2(a.z, a.z), pack2(a.w, a.w)};
            #pragma unroll
            for (int i = 0; i < 4; i++)
                #pragma unroll
                for (int j = 0; j < 4; j++)
                    ffma2(acc[i][j], ap[i], bp[j]);
        }
        __syncthreads();
    }
    #pragma unroll
    for (int i = 0; i < 4; i++) {
        int o = o0 + ty4 + i;
        if (o < Cout) {
            float bvv = bias[o];
            float* op = out + ((size_t)b * Cout + o) * NN + n0;
            float2 p0 = unpack2(acc[i][0]), p1 = unpack2(acc[i][1]);
            float2 p2 = unpack2(acc[i][2]), p3 = unpack2(acc[i][3]);
            *(float4*)&op[tx4] =
                make_float4(p0.x + bvv, p0.y + bvv, p1.x + bvv, p1.y + bvv);
            *(float4*)&op[32 + tx4] =
                make_float4(p2.x + bvv, p2.y + bvv, p3.x + bvv, p3.y + bvv);
        }
    }
}

// ---------------- instance norm per (b,c) row over N; optional act + residual
// act: 0 none, 1 exact gelu, 2 relu
__global__ __launch_bounds__(256) void inorm_kernel(
    const float* __restrict__ in, float* __restrict__ out,
    const float* __restrict__ res, int act)
{
    int row = blockIdx.x;
    const float* p = in + (size_t)row * NN;
    int tid = threadIdx.x;
    float s = 0.f, s2 = 0.f;
    for (int i = tid; i < NN; i += 256) { float v = p[i]; s += v; s2 += v * v; }
    __shared__ float r0s[256], r1s[256];
    r0s[tid] = s; r1s[tid] = s2;
    __syncthreads();
    for (int st = 128; st > 0; st >>= 1) {
        if (tid < st) { r0s[tid] += r0s[tid + st]; r1s[tid] += r1s[tid + st]; }
        __syncthreads();
    }
    __shared__ float msh, rsh;
    if (tid == 0) {
        float mean = r0s[0] * (1.f / NN);
        float var  = r1s[0] * (1.f / NN) - mean * mean;
        msh = mean; rsh = rsqrtf(var + EPS_);
    }
    __syncthreads();
    float mean = msh, rstd = rsh;
    const float* rq = res ? res + (size_t)row * NN : nullptr;
    float* op = out + (size_t)row * NN;
    for (int i = tid; i < NN; i += 256) {
        float v = (p[i] - mean) * rstd;
        if (act == 1) v = 0.5f * v * (1.f + erff(v * 0.70710678118654752f));
        else if (act == 2) v = fmaxf(v, 0.f);
        if (rq) v += rq[i];
        op[i] = v;
    }
}

// ---------------- l2 normalize over channel dim per (b,n); also emit sq = ||xn||^2
__global__ __launch_bounds__(256) void l2norm_kernel(
    const float* __restrict__ xf, float* __restrict__ xn, float* __restrict__ sq)
{
    int t = blockIdx.x * 256 + threadIdx.x;
    if (t >= BB * NN) return;
    int b = t / NN, n = t - b * NN;
    const float* p = xf + (size_t)b * CC * NN + n;
    float s = 0.f;
    #pragma unroll 16
    for (int c = 0; c < CC; c++) { float v = p[(size_t)c * NN]; s += v * v; }
    float inv = 1.f / fmaxf(sqrtf(s), 1e-12f);
    float* q = xn + (size_t)b * CC * NN + n;
    #pragma unroll 16
    for (int c = 0; c < CC; c++) q[(size_t)c * NN] = p[(size_t)c * NN] * inv;
    sq[t] = s * inv * inv;
}

// ---------------- fused pairwise distance + top-9 smallest
// block 128 threads, 64 n-rows, m-tiles of 64
// thread = 4 n-rows x 8 m-cols; rows via one LDS.128 (quarter-warp broadcast),
// m-cols as two LDS.128 reinterpreted as f32x2 pairs; FFMA2 mainloop.
__device__ __forceinline__ void tk_insert(float v, int m, float* tv, int* ti,
                                          float& wv, int& wi)
{
    if (v < wv) {
        tv[wi] = v; ti[wi] = m;
        wv = tv[0]; wi = 0;
        #pragma unroll
        for (int k = 1; k < KK; k++) if (tv[k] > wv) { wv = tv[k]; wi = k; }
    }
}

__global__ __launch_bounds__(128) void dist_topk_kernel(
    const float* __restrict__ xn, const float* __restrict__ sq,
    const float* __restrict__ rp, int* __restrict__ oidx)
{
    int b = blockIdx.y;
    int n0 = blockIdx.x * 64;
    int tid = threadIdx.x;
    int mr  = tid >> 3;        // 0..15
    int mc4 = (tid & 7) * 4;   // 0..28
    int rbase = mr * 4;        // rows rbase..rbase+3 (0..63)

    __shared__ float Xn_s[CC * 64];   // 24 KB, [c][64 n-rows]
    __shared__ float sh2[CC * 64];    // 24 KB, [c][64 m]; reused for merge

    const float* xb = xn + (size_t)b * CC * NN;
    for (int t = tid; t < CC * 16; t += 128) {
        int c = t >> 4, q = (t & 15) * 4;
        *(float4*)&Xn_s[c * 64 + q] = *(const float4*)&xb[(size_t)c * NN + n0 + q];
    }
    __syncthreads();

    float4 sqn4 = *(const float4*)&sq[b * NN + n0 + rbase];
    float sqn[4] = {sqn4.x, sqn4.y, sqn4.z, sqn4.w};

    float tv[4][KK]; int ti[4][KK];
    float wv[4]; int wi[4];
    #pragma unroll
    for (int i = 0; i < 4; i++) {
        #pragma unroll
        for (int k = 0; k < KK; k++) { tv[i][k] = 1e30f; ti[i][k] = 0; }
        wv[i] = 1e30f; wi[i] = 0;
    }

    for (int m0 = 0; m0 < NN; m0 += 64) {
        __syncthreads();
        for (int t = tid; t < CC * 16; t += 128) {
            int c = t >> 4, q = (t & 15) * 4;
            *(float4*)&sh2[c * 64 + q] = *(const float4*)&xb[(size_t)c * NN + m0 + q];
        }
        __syncthreads();
        ull acc[4][4];
        #pragma unroll
        for (int i = 0; i < 4; i++)
            #pragma unroll
            for (int j = 0; j < 4; j++) acc[i][j] = 0ull;
        #pragma unroll 4
        for (int c = 0; c < CC; c++) {
            float4 a = *(const float4*)&Xn_s[c * 64 + rbase];           // broadcast
            ulonglong2 blp = *(const ulonglong2*)&sh2[c * 64 + mc4];    // free pairs
            ulonglong2 brp = *(const ulonglong2*)&sh2[c * 64 + 32 + mc4];
            ull bp[4] = {blp.x, blp.y, brp.x, brp.y};
            ull ap[4] = {pack2(a.x, a.x), pack2(a.y, a.y),
                         pack2(a.z, a.z), pack2(a.w, a.w)};
            #pragma unroll
            for (int i = 0; i < 4; i++)
                #pragma unroll
                for (int j = 0; j < 4; j++)
                    ffma2(acc[i][j], ap[i], bp[j]);
        }
        // epilogue: dist + topk insert (all 16B-aligned vector loads)
        const float* sqm = sq + b * NN + m0;
        float4 sqL = *(const float4*)&sqm[mc4];
        float4 sqR = *(const float4*)&sqm[32 + mc4];
        float sv[8] = {sqL.x, sqL.y, sqL.z, sqL.w, sqR.x, sqR.y, sqR.z, sqR.w};
        #pragma unroll
        for (int i = 0; i < 4; i++) {
            const float* rpr = rp + (size_t)(n0 + rbase + i) * NN + m0;
            float4 rL = *(const float4*)&rpr[mc4];
            float4 rR = *(const float4*)&rpr[32 + mc4];
            float rv[8] = {rL.x, rL.y, rL.z, rL.w, rR.x, rR.y, rR.z, rR.w};
            float2 p01 = unpack2(acc[i][0]);
            float2 p23 = unpack2(acc[i][1]);
            float2 p45 = unpack2(acc[i][2]);
            float2 p67 = unpack2(acc[i][3]);
            float dot[8] = {p01.x, p01.y, p23.x, p23.y, p45.x, p45.y, p67.x, p67.y};
            float base = sqn[i];
            #pragma unroll
            for (int j = 0; j < 8; j++) {
                int m = m0 + (j < 4 ? mc4 + j : 32 + mc4 + (j - 4));
                float d = fmaf(-2.f, dot[j], base + sv[j] + rv[j]);
                tk_insert(d, m, tv[i], ti[i], wv[i], wi[i]);
            }
        }
    }

    // ---------- merge: two passes of 32 rows using sh2 ----------
    __syncthreads();
    float* cv = sh2;                          // [32][8][9] values
    int*   ci = (int*)(sh2 + 32 * 8 * KK);    // [32][8][9] indices
    int mc = tid & 7;
    #pragma unroll 1
    for (int pass = 0; pass < 2; pass++) {
        if ((mr >> 3) == pass) {
            int lr = rbase - pass * 32;       // 0..28
            #pragma unroll
            for (int i = 0; i < 4; i++)
                #pragma unroll
                for (int k = 0; k < KK; k++) {
                    cv[((lr + i) * 8 + mc) * KK + k] = tv[i][k];
                    ci[((lr + i) * 8 + mc) * KK + k] = ti[i][k];
                }
        }
        __syncthreads();
        if (tid < 32) {
            float* rv = cv + tid * 8 * KK;
            int*   ri = ci + tid * 8 * KK;
            int* op = oidx + ((size_t)b * NN + n0 + pass * 32 + tid) * KK;
            for (int k = 0; k < KK; k++) {
                float best = 2e30f; int bi = 0, bt = 0;
                for (int t = 0; t < 8 * KK; t++) {
                    float v = rv[t];
                    if (v < best) { best = v; bi = ri[t]; bt = t; }
                }
                rv[bt] = 3e30f;   // consume
                op[k] = bi;
            }
        }
        __syncthreads();
    }
}

// ---------------- gather neighbors, max(x_j - x_i), write channel-interleaved (B,2C,N)
__global__ __launch_bounds__(256) void aggregate_kernel(
    const float* __restrict__ xf, const int* __restrict__ idx, float* __restrict__ y)
{
    int bc = blockIdx.x;            // b*CC + c
    __shared__ float row[NN];
    const float* p = xf + (size_t)bc * NN;
    for (int i = threadIdx.x; i < NN; i += 256) row[i] = p[i];
    __syncthreads();
    int b = bc / CC, c = bc - b * CC;
    const int* ip = idx + (size_t)b * NN * KK;
    float* y0 = y + ((size_t)b * C2 + 2 * c) * NN;
    float* y1 = y0 + NN;
    for (int n = threadIdx.x; n < NN; n += 256) {
        float xi = row[n];
        float mx = -3e38f;
        #pragma unroll
        for (int k = 0; k < KK; k++) {
            int j = ip[n * KK + k];
            mx = fmaxf(mx, row[j] - xi);
        }
        y0[n] = xi;
        y1[n] = mx;
    }
}

// ---------------- host orchestration ----------------
static void run_conv(const float* X, const float* W, const float* bias,
                     float* out, int Cout, int Cin)
{
    dim3 g(NN / 64, (Cout + 63) / 64, BB);
    gemm_bias_kernel<<<g, 128>>>(X, W, bias, out, Cout, Cin);
}
static void run_inorm(const float* in, float* out, const float* res, int Crows, int act)
{
    inorm_kernel<<<BB * Crows, 256>>>(in, out, res, act);
}

extern "C" void kernel_launch(void* const* d_in, const int* in_sizes, int n_in,
                              void* d_out, int out_size)
{
    (void)in_sizes; (void)n_in; (void)out_size;
    const float* x  = (const float*)d_in[0];
    const float* rp = (const float*)d_in[1];
    const float* P[20];
    for (int i = 0; i < 20; i++) P[i] = (const float*)d_in[2 + i];

    float *act, *t1, *xf, *xnp, *sqp, *big; int* idxp;
    cudaGetSymbolAddress((void**)&act,  g_act);
    cudaGetSymbolAddress((void**)&t1,   g_t1);
    cudaGetSymbolAddress((void**)&xf,   g_xf);
    cudaGetSymbolAddress((void**)&xnp,  g_xn);
    cudaGetSymbolAddress((void**)&sqp,  g_sq);
    cudaGetSymbolAddress((void**)&idxp, g_idx);
    cudaGetSymbolAddress((void**)&big,  g_big);
    float* y2 = big;                          // (B,2C,N)
    float* t3 = big + (size_t)BB * C2 * NN;   // (B,2C,N)
    float* out = (float*)d_out;

    auto grapher = [&](const float* inx,
                       const float* w1, const float* b1,
                       const float* mw, const float* mb,
                       const float* w2, const float* b2, float* outp) {
        run_conv(inx, w1, b1, t1, CC, CC);
        run_inorm(t1, xf, nullptr, CC, 0);                          // xf
        l2norm_kernel<<<(BB * NN + 255) / 256, 256>>>(xf, xnp, sqp);
        dim3 dg(NN / 64, BB);
        dist_topk_kernel<<<dg, 128>>>(xnp, sqp, rp, idxp);
        aggregate_kernel<<<BB * CC, 256>>>(xf, idxp, y2);           // (B,2C,N)
        run_conv(y2, mw, mb, t3, C2, C2);
        run_inorm(t3, t3, nullptr, C2, 1);                          // gelu, in-place
        run_conv(t3, w2, b2, t1, CC, C2);
        run_inorm(t1, outp, inx, CC, 0);                            // + shortcut
    };
    auto ffn = [&](float* a, const float* w1, const float* b1,
                   const float* w2, const float* b2) {
        run_conv(a, w1, b1, big, C4, CC);
        run_inorm(big, big, nullptr, C4, 1);                        // gelu, in-place
        run_conv(big, w2, b2, t1, CC, C4);
        run_inorm(t1, a, a, CC, 0);                                 // + shortcut
    };

    grapher(x, P[0], P[1], P[2], P[3], P[4], P[5], act);
    ffn(act, P[12], P[13], P[14], P[15]);
    run_inorm(act, act, nullptr, CC, 2);                            // relu(inorm)
    grapher(act, P[6], P[7], P[8], P[9], P[10], P[11], act);
    ffn(act, P[16], P[17], P[18], P[19]);
    run_inorm(act, out, x, CC, 0);                                  // x + inorm(y)
}